// round 1
// baseline (speedup 1.0000x reference)
#include <cuda_runtime.h>
#include <math.h>
#include <stdint.h>

// ---------------------------------------------------------------------------
// Problem constants
//   inp0: (8, 2048, 768)   inp1: (8, 1024, 1536)   attn_mask: (8, 64)
//   Level 0 uses heads 0:6  -> W columns   0:384
//   Level 1 uses heads 6:12 -> W columns 384:768
//   Output: (8, 2048, 768) fp32  followed by mask (2, 2048) fp32
// ---------------------------------------------------------------------------
#define B        8
#define N0       2048
#define N1       1024
#define HD       384          // 6 heads * 64
#define D        64
#define NH       6
#define M0       (B * N0)     // 16384
#define M1       (B * N1)     // 8192
#define OUT_ELEMS ((size_t)B * N0 * 768)

// Scratch (device globals: allocation-free contract)
__device__ __align__(128) float g_q0[M0 * HD];
__device__ __align__(128) float g_k0[M0 * HD];
__device__ __align__(128) float g_v0[M0 * HD];
__device__ __align__(128) float g_q1[M1 * HD];
__device__ __align__(128) float g_k1[M1 * HD];
__device__ __align__(128) float g_v1[M1 * HD];
__device__ __align__(128) float g_o0[M0 * HD];
__device__ __align__(128) float g_o1[M1 * HD];

// ---------------------------------------------------------------------------
// 128x128x8 register-tiled SGEMM.
//   C[M, N] = A[M, K] @ W[K(rows), wOff + n]  (+ epilogue)
// mode 0: C = acc + bias[col]
// mode 1: C = (acc + bias[col]) * 0.125 + mask[(row/nseqA)*64 + (col&63)]
// mode 2: C[remapped row] += acc          (row remap: (r/nseqA)*nseqC + r%nseqA)
// All dims must be multiples of tile sizes (true for this problem).
// ---------------------------------------------------------------------------
__global__ __launch_bounds__(256) void sgemm128(
    const float* __restrict__ A, int K,
    const float* __restrict__ W, int ldw, int wOff,
    const float* __restrict__ bias,
    float* __restrict__ C, int ldc,
    int mode, const float* __restrict__ mask,
    int nseqA, int nseqC)
{
    __shared__ float As[8 * 128];
    __shared__ float Bs[8 * 128];

    const int tid = threadIdx.x;
    const int tx = tid & 15;
    const int ty = tid >> 4;
    const int m0 = blockIdx.y * 128;
    const int n0 = blockIdx.x * 128;

    const float* Ab = A + (size_t)m0 * K;
    const float* Wb = W + wOff + n0;

    float acc[8][8];
#pragma unroll
    for (int i = 0; i < 8; i++)
#pragma unroll
        for (int j = 0; j < 8; j++) acc[i][j] = 0.f;

    const int aRow = tid >> 1;           // 0..127
    const int aK4  = (tid & 1) << 2;     // 0 or 4
    const int bRow = tid >> 5;           // 0..7
    const int bCol = (tid & 31) << 2;    // 0..124

    for (int k0 = 0; k0 < K; k0 += 8) {
        float4 a4 = *(const float4*)(Ab + (size_t)aRow * K + k0 + aK4);
        As[(aK4 + 0) * 128 + aRow] = a4.x;
        As[(aK4 + 1) * 128 + aRow] = a4.y;
        As[(aK4 + 2) * 128 + aRow] = a4.z;
        As[(aK4 + 3) * 128 + aRow] = a4.w;
        *(float4*)&Bs[bRow * 128 + bCol] =
            *(const float4*)(Wb + (size_t)(k0 + bRow) * ldw + bCol);
        __syncthreads();

#pragma unroll
        for (int kk = 0; kk < 8; kk++) {
            float4 a0 = *(const float4*)&As[kk * 128 + ty * 8];
            float4 a1 = *(const float4*)&As[kk * 128 + ty * 8 + 4];
            float4 b0 = *(const float4*)&Bs[kk * 128 + tx * 8];
            float4 b1 = *(const float4*)&Bs[kk * 128 + tx * 8 + 4];
            float av[8] = {a0.x, a0.y, a0.z, a0.w, a1.x, a1.y, a1.z, a1.w};
            float bv[8] = {b0.x, b0.y, b0.z, b0.w, b1.x, b1.y, b1.z, b1.w};
#pragma unroll
            for (int i = 0; i < 8; i++)
#pragma unroll
                for (int j = 0; j < 8; j++)
                    acc[i][j] += av[i] * bv[j];
        }
        __syncthreads();
    }

    // Epilogue
#pragma unroll
    for (int i = 0; i < 8; i++) {
        int grow = m0 + ty * 8 + i;
        int orow = (grow / nseqA) * nseqC + (grow % nseqA);
        int bidx = (grow / nseqA) * 64;
#pragma unroll
        for (int j = 0; j < 8; j++) {
            int col = n0 + tx * 8 + j;
            float c = acc[i][j];
            if (mode == 0) {
                c += bias[col];
            } else if (mode == 1) {
                c = (c + bias[col]) * 0.125f + mask[bidx + (col & 63)];
            } else {  // mode 2: accumulate
                c += C[(size_t)orow * ldc + col];
            }
            C[(size_t)orow * ldc + col] = c;
        }
    }
}

// ---------------------------------------------------------------------------
// Flash attention, 64-row query tile per block, d = 64, 6 heads packed into
// [B, N, 384] buffers (col = h*64 + d). 256 threads, 4x4 register tile per
// thread for both S and O. Online softmax. Padded (68) smem rows for
// conflict-free float4 reads.
// ---------------------------------------------------------------------------
#define PAD 68
#define ATTN_SMEM_BYTES (4 * 64 * PAD * 4)

__global__ __launch_bounds__(256) void attn_kernel(
    const float* __restrict__ qm, const float* __restrict__ km,
    const float* __restrict__ vm, float* __restrict__ om, int Nq)
{
    extern __shared__ float sm[];
    float* Qs = sm;                  // [64][PAD]  rows = query, cols = d
    float* Ks = sm + 64 * PAD;       // [64][PAD]  rows = key,   cols = d
    float* Vt = sm + 2 * 64 * PAD;   // [64][PAD]  rows = d(out col), cols = m
    float* Ps = sm + 3 * 64 * PAD;   // [64][PAD]  rows = query, cols = m

    const int tid = threadIdx.x;
    const int tx = tid & 15;
    const int ty = tid >> 4;
    const int bh = blockIdx.y;
    const int b = bh / NH, h = bh % NH;
    const int n0 = blockIdx.x * 64;
    const size_t base = (size_t)b * Nq * HD + h * D;

    // load Q tile (float4)
    for (int i = tid; i < 1024; i += 256) {
        int r = i >> 4, c4 = (i & 15) << 2;
        *(float4*)&Qs[r * PAD + c4] =
            *(const float4*)(qm + base + (size_t)(n0 + r) * HD + c4);
    }

    const int r0 = ty * 4, c0 = tx * 4;
    float mrow[4], lrow[4], Oa[4][4];
#pragma unroll
    for (int i = 0; i < 4; i++) {
        mrow[i] = -1e30f;
        lrow[i] = 0.f;
#pragma unroll
        for (int j = 0; j < 4; j++) Oa[i][j] = 0.f;
    }

    for (int m0 = 0; m0 < Nq; m0 += 64) {
        // load K tile (row = key, col = d), V transposed (row = d, col = key)
        for (int i = tid; i < 1024; i += 256) {
            int r = i >> 4, c4 = (i & 15) << 2;
            *(float4*)&Ks[r * PAD + c4] =
                *(const float4*)(km + base + (size_t)(m0 + r) * HD + c4);
        }
        for (int i = tid; i < 4096; i += 256) {
            int c = i & 63, r = i >> 6;
            Vt[c * PAD + r] = vm[base + (size_t)(m0 + r) * HD + c];
        }
        __syncthreads();

        // S = Q K^T  (4x4 per thread)
        float s[4][4];
#pragma unroll
        for (int i = 0; i < 4; i++)
#pragma unroll
            for (int j = 0; j < 4; j++) s[i][j] = 0.f;

#pragma unroll 4
        for (int d4 = 0; d4 < 64; d4 += 4) {
            float4 qf[4], kf[4];
#pragma unroll
            for (int i = 0; i < 4; i++) qf[i] = *(const float4*)&Qs[(r0 + i) * PAD + d4];
#pragma unroll
            for (int j = 0; j < 4; j++) kf[j] = *(const float4*)&Ks[(c0 + j) * PAD + d4];
#pragma unroll
            for (int i = 0; i < 4; i++)
#pragma unroll
                for (int j = 0; j < 4; j++)
                    s[i][j] += qf[i].x * kf[j].x + qf[i].y * kf[j].y +
                               qf[i].z * kf[j].z + qf[i].w * kf[j].w;
        }

        // online softmax (row groups span one 16-lane half-warp: same ty)
#pragma unroll
        for (int i = 0; i < 4; i++) {
            float mx = fmaxf(fmaxf(s[i][0], s[i][1]), fmaxf(s[i][2], s[i][3]));
#pragma unroll
            for (int off = 8; off > 0; off >>= 1)
                mx = fmaxf(mx, __shfl_xor_sync(0xffffffffu, mx, off));
            float mnew = fmaxf(mrow[i], mx);
            float corr = __expf(mrow[i] - mnew);
            float rs = 0.f;
#pragma unroll
            for (int j = 0; j < 4; j++) {
                float p = __expf(s[i][j] - mnew);
                s[i][j] = p;
                rs += p;
            }
#pragma unroll
            for (int off = 8; off > 0; off >>= 1)
                rs += __shfl_xor_sync(0xffffffffu, rs, off);
            lrow[i] = lrow[i] * corr + rs;
            mrow[i] = mnew;
#pragma unroll
            for (int j = 0; j < 4; j++) Oa[i][j] *= corr;
        }

        // publish P tile
#pragma unroll
        for (int i = 0; i < 4; i++)
            *(float4*)&Ps[(r0 + i) * PAD + c0] =
                make_float4(s[i][0], s[i][1], s[i][2], s[i][3]);
        __syncthreads();

        // O += P @ V
#pragma unroll 4
        for (int m4 = 0; m4 < 64; m4 += 4) {
            float4 pf[4], vf[4];
#pragma unroll
            for (int i = 0; i < 4; i++) pf[i] = *(const float4*)&Ps[(r0 + i) * PAD + m4];
#pragma unroll
            for (int j = 0; j < 4; j++) vf[j] = *(const float4*)&Vt[(c0 + j) * PAD + m4];
#pragma unroll
            for (int i = 0; i < 4; i++)
#pragma unroll
                for (int j = 0; j < 4; j++)
                    Oa[i][j] += pf[i].x * vf[j].x + pf[i].y * vf[j].y +
                                pf[i].z * vf[j].z + pf[i].w * vf[j].w;
        }
        __syncthreads();
    }

    // normalize + store (merged layout: col = h*64 + d)
#pragma unroll
    for (int i = 0; i < 4; i++) {
        float inv = 1.f / lrow[i];
#pragma unroll
        for (int j = 0; j < 4; j++)
            om[base + (size_t)(n0 + r0 + i) * HD + c0 + j] = Oa[i][j] * inv;
    }
}

// ---------------------------------------------------------------------------
// Output mask: [2, 2048]; level 0 all ones, level 1 first 1024 ones.
// ---------------------------------------------------------------------------
__global__ void mask_kernel(float* __restrict__ out)
{
    int i = blockIdx.x * blockDim.x + threadIdx.x;
    if (i < 2 * N0) {
        int lvl = i >> 11, n = i & (N0 - 1);
        out[i] = (lvl == 0 || n < N1) ? 1.f : 0.f;
    }
}

// ---------------------------------------------------------------------------
extern "C" void kernel_launch(void* const* d_in, const int* in_sizes, int n_in,
                              void* d_out, int out_size)
{
    (void)in_sizes; (void)n_in; (void)out_size;
    const float* inp0  = (const float*)d_in[0];
    const float* inp1  = (const float*)d_in[1];
    const float* amask = (const float*)d_in[2];
    const float* Wq0 = (const float*)d_in[3];
    const float* bq0 = (const float*)d_in[4];
    const float* Wk0 = (const float*)d_in[5];
    const float* bk0 = (const float*)d_in[6];
    const float* Wv0 = (const float*)d_in[7];
    const float* bv0 = (const float*)d_in[8];
    const float* Wq1 = (const float*)d_in[9];
    const float* bq1 = (const float*)d_in[10];
    const float* Wk1 = (const float*)d_in[11];
    const float* bk1 = (const float*)d_in[12];
    const float* Wv1 = (const float*)d_in[13];
    const float* bv1 = (const float*)d_in[14];
    const float* Wo  = (const float*)d_in[15];
    const float* bo  = (const float*)d_in[16];
    float* out = (float*)d_out;

    float *q0, *k0, *v0, *q1, *k1, *v1, *o0, *o1;
    cudaGetSymbolAddress((void**)&q0, g_q0);
    cudaGetSymbolAddress((void**)&k0, g_k0);
    cudaGetSymbolAddress((void**)&v0, g_v0);
    cudaGetSymbolAddress((void**)&q1, g_q1);
    cudaGetSymbolAddress((void**)&k1, g_k1);
    cudaGetSymbolAddress((void**)&v1, g_v1);
    cudaGetSymbolAddress((void**)&o0, g_o0);
    cudaGetSymbolAddress((void**)&o1, g_o1);

    cudaFuncSetAttribute(attn_kernel,
                         cudaFuncAttributeMaxDynamicSharedMemorySize,
                         ATTN_SMEM_BYTES);

    dim3 blk(256);

    // Level-0 projections: (16384 x 768) @ W[:, 0:384]
    sgemm128<<<dim3(3, 128), blk>>>(inp0, 768, Wq0, 768, 0, bq0, q0, HD, 1, amask, N0, N0);
    sgemm128<<<dim3(3, 128), blk>>>(inp0, 768, Wk0, 768, 0, bk0, k0, HD, 0, nullptr, N0, N0);
    sgemm128<<<dim3(3, 128), blk>>>(inp0, 768, Wv0, 768, 0, bv0, v0, HD, 0, nullptr, N0, N0);
    // Level-1 projections: (8192 x 1536) @ W[:, 384:768]
    sgemm128<<<dim3(3, 64), blk>>>(inp1, 1536, Wq1, 768, 384, bq1 + 384, q1, HD, 1, amask, N1, N1);
    sgemm128<<<dim3(3, 64), blk>>>(inp1, 1536, Wk1, 768, 384, bk1 + 384, k1, HD, 0, nullptr, N1, N1);
    sgemm128<<<dim3(3, 64), blk>>>(inp1, 1536, Wv1, 768, 384, bv1 + 384, v1, HD, 0, nullptr, N1, N1);

    // Attention (per level)
    attn_kernel<<<dim3(N0 / 64, B * NH), blk, ATTN_SMEM_BYTES>>>(q0, k0, v0, o0, N0);
    attn_kernel<<<dim3(N1 / 64, B * NH), blk, ATTN_SMEM_BYTES>>>(q1, k1, v1, o1, N1);

    // Output projection: out = o0 @ Wo[0:384,:] + bo; rows n<1024 += o1 @ Wo[768:1152,:]
    sgemm128<<<dim3(6, 128), blk>>>(o0, HD, Wo, 768, 0, bo, out, 768, 0, nullptr, N0, N0);
    sgemm128<<<dim3(6, 64),  blk>>>(o1, HD, Wo + 768 * 768, 768, 0, nullptr, out, 768, 2, nullptr, N1, N0);

    // Mask tail
    mask_kernel<<<16, 256>>>(out + OUT_ELEMS);
}